// round 9
// baseline (speedup 1.0000x reference)
#include <cuda_runtime.h>
#include <math.h>

#define Bsz  2
#define Nseq 2048
#define Emb  1024
#define Hh   16
#define Dd   64
#define Mrows (Bsz * Nseq)      // 4096
#define E3   (3 * Emb)          // 3072

// Scratch (device globals). ALL accesses scalar (R1-proven envelope).
__device__ float g_q[Bsz * Hh * Nseq * Dd];   // [B,H,N,D]
__device__ float g_k[Bsz * Hh * Nseq * Dd];
__device__ float g_v[Bsz * Hh * Nseq * Dd];
__device__ float g_ao[Mrows * Emb];           // attention out [B*N, E]

// ---------------------------------------------------------------------------
// QKV GEMM: [4096,1024] @ [1024,3072] + bias -> scatter to Q/K/V [B,H,N,D]
// Tile 128x128, BK=16, 256 threads, 8x8 microtile on strided column/row sets:
//   thread rows {16i+ty}, cols {16j+tx}  (ty=tid>>4, tx=tid&15)
// Odd stride 129 => B-side scalar LDS = 16 distinct banks (1 phase),
// A-side = 2-address broadcast (1 phase).
// ---------------------------------------------------------------------------
__global__ __launch_bounds__(256) void qkv_gemm8(
    const float* __restrict__ X, const float* __restrict__ Wq,
    const float* __restrict__ bias)
{
    __shared__ float As[16 * 129];   // [k][m], stride 129
    __shared__ float Bs[16 * 129];   // [k][n], stride 129

    const int tid = threadIdx.x;
    const int tx  = tid & 15;
    const int ty  = tid >> 4;
    const int m0  = blockIdx.y * 128;
    const int n0  = blockIdx.x * 128;

    float acc[8][8] = {};

    for (int k0 = 0; k0 < Emb; k0 += 16) {
        #pragma unroll
        for (int u = 0; u < 8; u++) {
            const int e = tid + u * 256;               // 0..2047
            As[(e & 15) * 129 + (e >> 4)] = X[(m0 + (e >> 4)) * Emb + k0 + (e & 15)];
            const int r = e >> 7, c = e & 127;
            Bs[r * 129 + c] = Wq[(k0 + r) * E3 + n0 + c];
        }
        __syncthreads();

        #pragma unroll
        for (int kk = 0; kk < 16; kk++) {
            float a[8], b[8];
            #pragma unroll
            for (int i = 0; i < 8; i++) a[i] = As[kk * 129 + 16 * i + ty];
            #pragma unroll
            for (int j = 0; j < 8; j++) b[j] = Bs[kk * 129 + 16 * j + tx];
            #pragma unroll
            for (int i = 0; i < 8; i++)
                #pragma unroll
                for (int j = 0; j < 8; j++)
                    acc[i][j] += a[i] * b[j];
        }
        __syncthreads();
    }

    #pragma unroll
    for (int i = 0; i < 8; i++) {
        const int row = m0 + 16 * i + ty;
        const int bb  = row >> 11;
        const int tok = row & (Nseq - 1);
        #pragma unroll
        for (int j = 0; j < 8; j++) {
            const int col = n0 + 16 * j + tx;
            const float v = acc[i][j] + bias[col];
            const int part = col >> 10;               // 0=q,1=k,2=v
            const int h    = (col >> 6) & (Hh - 1);
            const int d    = col & (Dd - 1);
            float* dst = (part == 0) ? g_q : ((part == 1) ? g_k : g_v);
            dst[(((bb * Hh + h) * Nseq) + tok) * Dd + d] = v;
        }
    }
}

// ---------------------------------------------------------------------------
// Output projection: [4096,1024] @ [1024,1024] + bias -> d_out. Same scheme.
// ---------------------------------------------------------------------------
__global__ __launch_bounds__(256) void proj_gemm8(
    const float* __restrict__ Wp, const float* __restrict__ bias,
    float* __restrict__ out)
{
    __shared__ float As[16 * 129];
    __shared__ float Bs[16 * 129];

    const int tid = threadIdx.x;
    const int tx  = tid & 15;
    const int ty  = tid >> 4;
    const int m0  = blockIdx.y * 128;
    const int n0  = blockIdx.x * 128;

    float acc[8][8] = {};

    for (int k0 = 0; k0 < Emb; k0 += 16) {
        #pragma unroll
        for (int u = 0; u < 8; u++) {
            const int e = tid + u * 256;
            As[(e & 15) * 129 + (e >> 4)] = g_ao[(m0 + (e >> 4)) * Emb + k0 + (e & 15)];
            const int r = e >> 7, c = e & 127;
            Bs[r * 129 + c] = Wp[(k0 + r) * Emb + n0 + c];
        }
        __syncthreads();

        #pragma unroll
        for (int kk = 0; kk < 16; kk++) {
            float a[8], b[8];
            #pragma unroll
            for (int i = 0; i < 8; i++) a[i] = As[kk * 129 + 16 * i + ty];
            #pragma unroll
            for (int j = 0; j < 8; j++) b[j] = Bs[kk * 129 + 16 * j + tx];
            #pragma unroll
            for (int i = 0; i < 8; i++)
                #pragma unroll
                for (int j = 0; j < 8; j++)
                    acc[i][j] += a[i] * b[j];
        }
        __syncthreads();
    }

    #pragma unroll
    for (int i = 0; i < 8; i++) {
        const int row = m0 + 16 * i + ty;
        #pragma unroll
        for (int j = 0; j < 8; j++) {
            const int col = n0 + 16 * j + tx;
            out[row * Emb + col] = acc[i][j] + bias[col];
        }
    }
}

// ---------------------------------------------------------------------------
// Flash attention, fp32. Block = one (b,h) x 64-query tile, 128 threads.
// Microtile 8 rows x 4 keys: rows {8ty+i} (ty=tid>>4, 0..7),
// key/d columns {16j+tx} (tx=tid&15, j=0..3). Stride 65 => all B-side scalar
// LDS conflict-free; A-side broadcast. Softmax per row over 16-lane group.
// ---------------------------------------------------------------------------
#define SW 65
#define ATTN_SMEM (4 * 64 * SW * 4)   // 66560 B (R1-proven value)

__global__ __launch_bounds__(128) void attn_kernel8()
{
    extern __shared__ float sm[];
    float* Qs = sm;                   // [64][65]  [q][d]
    float* Ks = sm + 64 * SW;         // [64][65]  [key][d]
    float* Vs = sm + 2 * 64 * SW;     // [64][65]  [key][d]
    float* Ps = sm + 3 * 64 * SW;     // [64][65]  [q][key]

    const int tid = threadIdx.x;
    const int tx  = tid & 15;
    const int ty  = tid >> 4;         // 0..7
    const int bh  = blockIdx.y;       // 0..31  (b*16+h)
    const int q0  = blockIdx.x * 64;

    const float* Qg = g_q + (bh * Nseq + q0) * Dd;
    const float* Kg = g_k + (size_t)bh * Nseq * Dd;
    const float* Vg = g_v + (size_t)bh * Nseq * Dd;

    // load Q tile [64][64], scalar
    #pragma unroll
    for (int u = 0; u < 32; u++) {
        const int e = tid + u * 128;
        Qs[(e >> 6) * SW + (e & 63)] = Qg[e];
    }

    float m_i[8], l_i[8], o[8][4];
    #pragma unroll
    for (int i = 0; i < 8; i++) {
        m_i[i] = -INFINITY;
        l_i[i] = 0.0f;
        #pragma unroll
        for (int j = 0; j < 4; j++) o[i][j] = 0.0f;
    }
    __syncthreads();

    for (int t = 0; t < Nseq / 64; t++) {
        const float* Kt = Kg + t * 64 * Dd;
        const float* Vt = Vg + t * 64 * Dd;
        #pragma unroll
        for (int u = 0; u < 32; u++) {
            const int e = tid + u * 128;
            const int r = e >> 6, c = e & 63;
            Ks[r * SW + c] = Kt[e];
            Vs[r * SW + c] = Vt[e];
        }
        __syncthreads();

        // S = Q K^T : rows {8ty+i}, keys {16j+tx}
        float s[8][4] = {};
        #pragma unroll
        for (int kk = 0; kk < 64; kk++) {
            float a[8], b[4];
            #pragma unroll
            for (int i = 0; i < 8; i++) a[i] = Qs[(8 * ty + i) * SW + kk];
            #pragma unroll
            for (int j = 0; j < 4; j++) b[j] = Ks[(16 * j + tx) * SW + kk];
            #pragma unroll
            for (int i = 0; i < 8; i++)
                #pragma unroll
                for (int j = 0; j < 4; j++)
                    s[i][j] += a[i] * b[j];
        }

        // online softmax per row (16 lanes sharing ty = half-warp)
        #pragma unroll
        for (int i = 0; i < 8; i++) {
            #pragma unroll
            for (int j = 0; j < 4; j++) s[i][j] *= 0.125f;   // D^-0.5
            float mt = fmaxf(fmaxf(s[i][0], s[i][1]), fmaxf(s[i][2], s[i][3]));
            #pragma unroll
            for (int off = 8; off >= 1; off >>= 1)
                mt = fmaxf(mt, __shfl_xor_sync(0xffffffffu, mt, off));
            float nm = fmaxf(m_i[i], mt);
            float rs = 0.0f;
            #pragma unroll
            for (int j = 0; j < 4; j++) {
                s[i][j] = __expf(s[i][j] - nm);
                rs += s[i][j];
            }
            #pragma unroll
            for (int off = 8; off >= 1; off >>= 1)
                rs += __shfl_xor_sync(0xffffffffu, rs, off);
            float corr = __expf(m_i[i] - nm);                 // exp(-inf)=0 first iter
            l_i[i] = l_i[i] * corr + rs;
            m_i[i] = nm;
            #pragma unroll
            for (int j = 0; j < 4; j++) o[i][j] *= corr;
        }

        // stage P [q][key]; rows owned within one warp -> __syncwarp suffices
        #pragma unroll
        for (int i = 0; i < 8; i++)
            #pragma unroll
            for (int j = 0; j < 4; j++)
                Ps[(8 * ty + i) * SW + 16 * j + tx] = s[i][j];
        __syncwarp();

        // O += P @ V : rows {8ty+i}, d-cols {16j+tx}
        #pragma unroll
        for (int kk = 0; kk < 64; kk++) {
            float a[8], b[4];
            #pragma unroll
            for (int i = 0; i < 8; i++) a[i] = Ps[(8 * ty + i) * SW + kk];
            #pragma unroll
            for (int j = 0; j < 4; j++) b[j] = Vs[kk * SW + 16 * j + tx];
            #pragma unroll
            for (int i = 0; i < 8; i++)
                #pragma unroll
                for (int j = 0; j < 4; j++)
                    o[i][j] += a[i] * b[j];
        }
        __syncthreads();
    }

    // epilogue: normalize, write [B,N,H*D], scalar
    const int bb = bh >> 4;
    const int h  = bh & (Hh - 1);
    #pragma unroll
    for (int i = 0; i < 8; i++) {
        const float inv = 1.0f / l_i[i];
        const int row = q0 + 8 * ty + i;
        #pragma unroll
        for (int j = 0; j < 4; j++)
            g_ao[(bb * Nseq + row) * Emb + h * Dd + 16 * j + tx] = o[i][j] * inv;
    }
}

// ---------------------------------------------------------------------------
extern "C" void kernel_launch(void* const* d_in, const int* in_sizes, int n_in,
                              void* d_out, int out_size)
{
    const float* x      = (const float*)d_in[0];
    const float* w_qkv  = (const float*)d_in[1];
    const float* b_qkv  = (const float*)d_in[2];
    const float* w_proj = (const float*)d_in[3];
    const float* b_proj = (const float*)d_in[4];
    float* out = (float*)d_out;

    cudaFuncSetAttribute(attn_kernel8,
                         cudaFuncAttributeMaxDynamicSharedMemorySize, ATTN_SMEM);

    qkv_gemm8<<<dim3(E3 / 128, Mrows / 128), 256>>>(x, w_qkv, b_qkv);
    attn_kernel8<<<dim3(Nseq / 64, Bsz * Hh), 128, ATTN_SMEM>>>();
    proj_gemm8<<<dim3(Emb / 128, Mrows / 128), 256>>>(w_proj, b_proj, out);
}

// round 10
// speedup vs baseline: 2.6733x; 2.6733x over previous
#include <cuda_runtime.h>
#include <math.h>

#define Bsz  2
#define Nseq 2048
#define Emb  1024
#define Hh   16
#define Dd   64
#define Mrows 4096
#define E3   3072

// Scratch (device globals). ALL global-memory access in this file is SCALAR
// (ld/st .f32) — the empirically-safe envelope from R1/R9.
__device__ float g_q[Bsz * Hh * Nseq * Dd];   // [B,H,N,D]
__device__ float g_k[Bsz * Hh * Nseq * Dd];
__device__ float g_v[Bsz * Hh * Nseq * Dd];
__device__ float g_ao[Mrows * Emb];           // attention out [B*N, E]

// ---------------------------------------------------------------------------
// tf32 round-to-nearest-even in plain integer C (no cvt asm).
// ---------------------------------------------------------------------------
__device__ __forceinline__ float f2tff(float f) {
    unsigned u = __float_as_uint(f);
    u = u + 0xFFFu + ((u >> 13) & 1u);
    return __uint_as_float(u & 0xFFFFE000u);
}

// m16n8k8 tf32 mma on named float4 accumulator C##mt##nt
#define MMA1(mt, nt)                                                          \
    asm volatile(                                                             \
        "mma.sync.aligned.m16n8k8.row.col.f32.tf32.tf32.f32 "                 \
        "{%0,%1,%2,%3}, {%4,%5,%6,%7}, {%8,%9}, {%0,%1,%2,%3};\n"             \
        : "+f"(c##mt##nt.x), "+f"(c##mt##nt.y),                               \
          "+f"(c##mt##nt.z), "+f"(c##mt##nt.w)                                \
        : "r"(a##mt.x), "r"(a##mt.y), "r"(a##mt.z), "r"(a##mt.w),             \
          "r"(b##nt.x), "r"(b##nt.y))

// A fragment (row-major A in As[m][k], stride 36):
#define LDA(mt)                                                               \
    uint4 a##mt;                                                              \
    {                                                                         \
        const int r_ = wm + mt * 16 + g;                                      \
        a##mt.x = __float_as_uint(As[r_][kk + tig]);                          \
        a##mt.y = __float_as_uint(As[r_ + 8][kk + tig]);                      \
        a##mt.z = __float_as_uint(As[r_][kk + tig + 4]);                      \
        a##mt.w = __float_as_uint(As[r_ + 8][kk + tig + 4]);                  \
    }

// B fragment (col-major B stored Bs[k][n], stride 136):
#define LDB(nt)                                                               \
    uint2 b##nt;                                                              \
    {                                                                         \
        const int col_ = wn + nt * 8 + g;                                     \
        b##nt.x = __float_as_uint(Bs[kk + tig][col_]);                        \
        b##nt.y = __float_as_uint(Bs[kk + tig + 4][col_]);                    \
    }

#define DEF_C(mt)                                                             \
    float4 c##mt##0 = {0.f,0.f,0.f,0.f}, c##mt##1 = {0.f,0.f,0.f,0.f},        \
           c##mt##2 = {0.f,0.f,0.f,0.f}, c##mt##3 = {0.f,0.f,0.f,0.f};

__device__ __forceinline__ void qkv_store(int row, int col, float v) {
    const int part = col >> 10;           // 0=q,1=k,2=v
    const int h    = (col >> 6) & (Hh - 1);
    const int d    = col & (Dd - 1);
    const int bb   = row >> 11;
    const int tok  = row & (Nseq - 1);
    float* dst = (part == 0) ? g_q : ((part == 1) ? g_k : g_v);
    dst[(((bb * Hh + h) * Nseq) + tok) * Dd + d] = v;
}

#define EPIQ(mt, nt)                                                          \
    {                                                                         \
        const int row_ = m0 + wm + mt * 16 + g;                               \
        const int col_ = n0 + wn + nt * 8 + 2 * tig;                          \
        qkv_store(row_,     col_,     c##mt##nt.x + bias[col_]);              \
        qkv_store(row_,     col_ + 1, c##mt##nt.y + bias[col_ + 1]);          \
        qkv_store(row_ + 8, col_,     c##mt##nt.z + bias[col_]);              \
        qkv_store(row_ + 8, col_ + 1, c##mt##nt.w + bias[col_ + 1]);          \
    }

#define EPIP(mt, nt)                                                          \
    {                                                                         \
        const int row_ = m0 + wm + mt * 16 + g;                               \
        const int col_ = n0 + wn + nt * 8 + 2 * tig;                          \
        out[row_ * Emb + col_]           = c##mt##nt.x + bias[col_];          \
        out[row_ * Emb + col_ + 1]       = c##mt##nt.y + bias[col_ + 1];      \
        out[(row_ + 8) * Emb + col_]     = c##mt##nt.z + bias[col_];          \
        out[(row_ + 8) * Emb + col_ + 1] = c##mt##nt.w + bias[col_ + 1];      \
    }

// shared GEMM body bits
#define GEMM_IDX                                                              \
    const int tid  = threadIdx.x;                                             \
    const int lane = tid & 31;                                                \
    const int w    = tid >> 5;                                                \
    const int g    = lane >> 2;                                               \
    const int tig  = lane & 3;                                                \
    const int wm   = (w >> 2) * 64;                                           \
    const int wn   = (w & 3) * 32;                                            \
    const int m0   = blockIdx.y * 128;                                        \
    const int n0   = blockIdx.x * 128;

#define GEMM_MAINLOOP(Aexpr, Bexpr, Nw)                                       \
    for (int k0 = 0; k0 < Emb; k0 += 32) {                                    \
        _Pragma("unroll")                                                     \
        for (int u = 0; u < 16; u++) {                                        \
            const int e = tid + u * 256;                                      \
            const int r = e >> 5, cA = e & 31;                                \
            As[r][cA] = f2tff(Aexpr);                                         \
            const int rb = e >> 7, cB = e & 127;                              \
            Bs[rb][cB] = f2tff(Bexpr);                                        \
        }                                                                     \
        __syncthreads();                                                      \
        _Pragma("unroll")                                                     \
        for (int ks = 0; ks < 4; ks++) {                                      \
            const int kk = ks * 8;                                            \
            LDA(0) LDA(1) LDA(2) LDA(3)                                       \
            LDB(0) LDB(1) LDB(2) LDB(3)                                       \
            MMA1(0,0); MMA1(0,1); MMA1(0,2); MMA1(0,3);                       \
            MMA1(1,0); MMA1(1,1); MMA1(1,2); MMA1(1,3);                       \
            MMA1(2,0); MMA1(2,1); MMA1(2,2); MMA1(2,3);                       \
            MMA1(3,0); MMA1(3,1); MMA1(3,2); MMA1(3,3);                       \
        }                                                                     \
        __syncthreads();                                                      \
    }

// ---------------------------------------------------------------------------
// QKV GEMM: [4096,1024] @ [1024,3072] + bias -> scatter to Q/K/V. tf32 mma.
// Block tile 128x128, k-chunk 32, 8 warps (2m x 4n), warp tile 64x32.
// ---------------------------------------------------------------------------
__global__ __launch_bounds__(256) void qkv_mma(
    const float* __restrict__ X, const float* __restrict__ Wq,
    const float* __restrict__ bias)
{
    __shared__ float As[128][36];
    __shared__ float Bs[32][136];
    GEMM_IDX
    DEF_C(0) DEF_C(1) DEF_C(2) DEF_C(3)
    GEMM_MAINLOOP(X[(m0 + r) * Emb + k0 + cA], Wq[(k0 + rb) * E3 + n0 + cB], E3)
    EPIQ(0,0) EPIQ(0,1) EPIQ(0,2) EPIQ(0,3)
    EPIQ(1,0) EPIQ(1,1) EPIQ(1,2) EPIQ(1,3)
    EPIQ(2,0) EPIQ(2,1) EPIQ(2,2) EPIQ(2,3)
    EPIQ(3,0) EPIQ(3,1) EPIQ(3,2) EPIQ(3,3)
}

// ---------------------------------------------------------------------------
// Output projection: g_ao[4096,1024] @ [1024,1024] + bias -> d_out. tf32 mma.
// ---------------------------------------------------------------------------
__global__ __launch_bounds__(256) void proj_mma(
    const float* __restrict__ Wp, const float* __restrict__ bias,
    float* __restrict__ out)
{
    __shared__ float As[128][36];
    __shared__ float Bs[32][136];
    GEMM_IDX
    DEF_C(0) DEF_C(1) DEF_C(2) DEF_C(3)
    GEMM_MAINLOOP(g_ao[(m0 + r) * Emb + k0 + cA], Wp[(k0 + rb) * Emb + n0 + cB], Emb)
    EPIP(0,0) EPIP(0,1) EPIP(0,2) EPIP(0,3)
    EPIP(1,0) EPIP(1,1) EPIP(1,2) EPIP(1,3)
    EPIP(2,0) EPIP(2,1) EPIP(2,2) EPIP(2,3)
    EPIP(3,0) EPIP(3,1) EPIP(3,2) EPIP(3,3)
}

// ---------------------------------------------------------------------------
// Flash attention, tf32 mma. Block = 64 queries x (b,h); 4 warps x 16 queries.
// sQ[64][68] [q][d], sK[64][68] [key][d], sV[64][72] [key][d], sP[64][68] [q][key].
// All strides >= 64 and conflict-free for their fragment access patterns.
// ---------------------------------------------------------------------------
#define QS 68
#define KS 68
#define VS 72
#define PS 68
#define ATTN_SMEM (64 * (QS + KS + VS + PS) * 4)   // 70656 B

#define MMA_S(nt)                                                             \
    {                                                                         \
        unsigned bx = __float_as_uint(sK[(nt * 8 + g) * KS + kk + tig]);      \
        unsigned by = __float_as_uint(sK[(nt * 8 + g) * KS + kk + tig + 4]);  \
        asm volatile(                                                         \
            "mma.sync.aligned.m16n8k8.row.col.f32.tf32.tf32.f32 "             \
            "{%0,%1,%2,%3}, {%4,%5,%6,%7}, {%8,%9}, {%0,%1,%2,%3};\n"         \
            : "+f"(s##nt.x), "+f"(s##nt.y), "+f"(s##nt.z), "+f"(s##nt.w)      \
            : "r"(a0), "r"(a1), "r"(a2), "r"(a3), "r"(bx), "r"(by));          \
    }

#define MMA_O(nt)                                                             \
    {                                                                         \
        unsigned bx = __float_as_uint(sV[(kk + tig) * VS + nt * 8 + g]);      \
        unsigned by = __float_as_uint(sV[(kk + tig + 4) * VS + nt * 8 + g]);  \
        asm volatile(                                                         \
            "mma.sync.aligned.m16n8k8.row.col.f32.tf32.tf32.f32 "             \
            "{%0,%1,%2,%3}, {%4,%5,%6,%7}, {%8,%9}, {%0,%1,%2,%3};\n"         \
            : "+f"(o##nt.x), "+f"(o##nt.y), "+f"(o##nt.z), "+f"(o##nt.w)      \
            : "r"(a0), "r"(a1), "r"(a2), "r"(a3), "r"(bx), "r"(by));          \
    }

#define SMAX(nt)                                                              \
    { s##nt.x *= 0.125f; s##nt.y *= 0.125f; s##nt.z *= 0.125f; s##nt.w *= 0.125f; \
      mx0 = fmaxf(mx0, fmaxf(s##nt.x, s##nt.y));                              \
      mx1 = fmaxf(mx1, fmaxf(s##nt.z, s##nt.w)); }

#define SEXP(nt)                                                              \
    { s##nt.x = __expf(s##nt.x - nm0); s##nt.y = __expf(s##nt.y - nm0);       \
      s##nt.z = __expf(s##nt.z - nm1); s##nt.w = __expf(s##nt.w - nm1);       \
      sum0 += s##nt.x + s##nt.y; sum1 += s##nt.z + s##nt.w; }

#define OCORR(nt)                                                             \
    { o##nt.x *= corr0; o##nt.y *= corr0; o##nt.z *= corr1; o##nt.w *= corr1; }

#define PSTORE(nt)                                                            \
    { const int cc = nt * 8 + 2 * tig;                                        \
      sP[qr * PS + cc]           = f2tff(s##nt.x);                            \
      sP[qr * PS + cc + 1]       = f2tff(s##nt.y);                            \
      sP[(qr + 8) * PS + cc]     = f2tff(s##nt.z);                            \
      sP[(qr + 8) * PS + cc + 1] = f2tff(s##nt.w); }

#define OSTORE(nt)                                                            \
    { const int cc = nt * 8 + 2 * tig;                                        \
      dst0[cc]     = o##nt.x * inv0;                                          \
      dst0[cc + 1] = o##nt.y * inv0;                                          \
      dst1[cc]     = o##nt.z * inv1;                                          \
      dst1[cc + 1] = o##nt.w * inv1; }

__global__ __launch_bounds__(128) void attn_mma()
{
    extern __shared__ float sm[];
    float* sQ = sm;                    // [64][68]
    float* sK = sQ + 64 * QS;          // [64][68]
    float* sV = sK + 64 * KS;          // [64][72]
    float* sP = sV + 64 * VS;          // [64][68]

    const int tid  = threadIdx.x;
    const int lane = tid & 31;
    const int w    = tid >> 5;         // warp 0..3 -> queries [16w,16w+16)
    const int g    = lane >> 2;
    const int tig  = lane & 3;
    const int bh   = blockIdx.y;
    const int q0   = blockIdx.x * 64;
    const int qr   = w * 16 + g;

    const float* Qg = g_q + (size_t)(bh * Nseq + q0) * Dd;
    const float* Kg = g_k + (size_t)bh * Nseq * Dd;
    const float* Vg = g_v + (size_t)bh * Nseq * Dd;

    // load Q tile (scalar global loads, tf32-rounded)
    #pragma unroll
    for (int u = 0; u < 32; u++) {
        const int e = tid + u * 128;
        sQ[(e >> 6) * QS + (e & 63)] = f2tff(Qg[e]);
    }

    float m0r = -INFINITY, m1r = -INFINITY, l0 = 0.0f, l1 = 0.0f;
    float4 o0 = {0.f,0.f,0.f,0.f}, o1 = {0.f,0.f,0.f,0.f},
           o2 = {0.f,0.f,0.f,0.f}, o3 = {0.f,0.f,0.f,0.f},
           o4 = {0.f,0.f,0.f,0.f}, o5 = {0.f,0.f,0.f,0.f},
           o6 = {0.f,0.f,0.f,0.f}, o7 = {0.f,0.f,0.f,0.f};
    __syncthreads();

    for (int t = 0; t < Nseq / 64; t++) {
        const float* Kt = Kg + t * 64 * Dd;
        const float* Vt = Vg + t * 64 * Dd;
        #pragma unroll
        for (int u = 0; u < 32; u++) {
            const int e = tid + u * 128;
            const int r = e >> 6, c = e & 63;
            sK[r * KS + c] = f2tff(Kt[e]);
            sV[r * VS + c] = f2tff(Vt[e]);
        }
        __syncthreads();

        // S = Q @ K^T  (16q x 64key per warp)
        float4 s0 = {0.f,0.f,0.f,0.f}, s1 = {0.f,0.f,0.f,0.f},
               s2 = {0.f,0.f,0.f,0.f}, s3 = {0.f,0.f,0.f,0.f},
               s4 = {0.f,0.f,0.f,0.f}, s5 = {0.f,0.f,0.f,0.f},
               s6 = {0.f,0.f,0.f,0.f}, s7 = {0.f,0.f,0.f,0.f};
        #pragma unroll
        for (int ks = 0; ks < 8; ks++) {
            const int kk = ks * 8;
            const unsigned a0 = __float_as_uint(sQ[qr * QS + kk + tig]);
            const unsigned a1 = __float_as_uint(sQ[(qr + 8) * QS + kk + tig]);
            const unsigned a2 = __float_as_uint(sQ[qr * QS + kk + tig + 4]);
            const unsigned a3 = __float_as_uint(sQ[(qr + 8) * QS + kk + tig + 4]);
            MMA_S(0) MMA_S(1) MMA_S(2) MMA_S(3)
            MMA_S(4) MMA_S(5) MMA_S(6) MMA_S(7)
        }

        // online softmax (rows qr and qr+8; reduce over tig: shfl 1,2)
        float mx0 = -INFINITY, mx1 = -INFINITY;
        SMAX(0) SMAX(1) SMAX(2) SMAX(3) SMAX(4) SMAX(5) SMAX(6) SMAX(7)
        mx0 = fmaxf(mx0, __shfl_xor_sync(0xffffffffu, mx0, 1));
        mx0 = fmaxf(mx0, __shfl_xor_sync(0xffffffffu, mx0, 2));
        mx1 = fmaxf(mx1, __shfl_xor_sync(0xffffffffu, mx1, 1));
        mx1 = fmaxf(mx1, __shfl_xor_sync(0xffffffffu, mx1, 2));
        const float nm0 = fmaxf(m0r, mx0);
        const float nm1 = fmaxf(m1r, mx1);
        float sum0 = 0.0f, sum1 = 0.0f;
        SEXP(0) SEXP(1) SEXP(2) SEXP(3) SEXP(4) SEXP(5) SEXP(6) SEXP(7)
        sum0 += __shfl_xor_sync(0xffffffffu, sum0, 1);
        sum0 += __shfl_xor_sync(0xffffffffu, sum0, 2);
        sum1 += __shfl_xor_sync(0xffffffffu, sum1, 1);
        sum1 += __shfl_xor_sync(0xffffffffu, sum1, 2);
        const float corr0 = __expf(m0r - nm0);   // exp(-inf)=0 first iter
        const float corr1 = __expf(m1r - nm1);
        l0 = l0 * corr0 + sum0;
        l1 = l1 * corr1 + sum1;
        m0r = nm0; m1r = nm1;
        OCORR(0) OCORR(1) OCORR(2) OCORR(3) OCORR(4) OCORR(5) OCORR(6) OCORR(7)

        // stage P (tf32) into sP (each warp owns its 16 rows)
        PSTORE(0) PSTORE(1) PSTORE(2) PSTORE(3)
        PSTORE(4) PSTORE(5) PSTORE(6) PSTORE(7)
        __syncwarp();

        // O += P @ V  (16q x 64d per warp)
        #pragma unroll
        for (int kt = 0; kt < 8; kt++) {
            const int kk = kt * 8;
            const unsigned a0 = __float_as_uint(sP[qr * PS + kk + tig]);
            const unsigned a1 = __float_as_uint(sP[(qr + 8) * PS + kk + tig]);
            const unsigned a2 = __float_as_uint(sP[qr * PS + kk + tig + 4]);
            const unsigned a3 = __float_as_uint(sP[(qr + 8) * PS + kk + tig + 4]);
            MMA_O(0) MMA_O(1) MMA_O(2) MMA_O(3)
            MMA_O(4) MMA_O(5) MMA_O(6) MMA_O(7)
        }
        __syncthreads();
    }

    // epilogue: normalize + write [B,N,H*D] (scalar stores)
    const int bb = bh >> 4;
    const int h  = bh & (Hh - 1);
    const float inv0 = 1.0f / l0;
    const float inv1 = 1.0f / l1;
    const int row0 = q0 + qr;
    float* dst0 = &g_ao[(size_t)(bb * Nseq + row0) * Emb + h * Dd];
    float* dst1 = &g_ao[(size_t)(bb * Nseq + row0 + 8) * Emb + h * Dd];
    OSTORE(0) OSTORE(1) OSTORE(2) OSTORE(3)
    OSTORE(4) OSTORE(5) OSTORE(6) OSTORE(7)
}

// ---------------------------------------------------------------------------
extern "C" void kernel_launch(void* const* d_in, const int* in_sizes, int n_in,
                              void* d_out, int out_size)
{
    const float* x      = (const float*)d_in[0];
    const float* w_qkv  = (const float*)d_in[1];
    const float* b_qkv  = (const float*)d_in[2];
    const float* w_proj = (const float*)d_in[3];
    const float* b_proj = (const float*)d_in[4];
    float* out = (float*)d_out;

    cudaFuncSetAttribute(attn_mma,
                         cudaFuncAttributeMaxDynamicSharedMemorySize, ATTN_SMEM);

    qkv_mma<<<dim3(E3 / 128, Mrows / 128), 256>>>(x, w_qkv, b_qkv);
    attn_mma<<<dim3(Nseq / 64, Bsz * Hh), 128, ATTN_SMEM>>>();
    proj_mma<<<dim3(Emb / 128, Mrows / 128), 256>>>(w_proj, b_proj, out);
}

// round 12
// speedup vs baseline: 4.0024x; 1.4972x over previous
#include <cuda_runtime.h>
#include <cuda_fp16.h>
#include <math.h>

#define Bsz  2
#define Nseq 2048
#define Emb  1024
#define Hh   16
#define Dd   64
#define Mrows 4096
#define E3   3072

// Scratch (device globals). ALL global-memory access in this file is SCALAR.
__device__ float g_q[Bsz * Hh * Nseq * Dd];   // [B,H,N,D]
__device__ float g_k[Bsz * Hh * Nseq * Dd];
__device__ float g_v[Bsz * Hh * Nseq * Dd];
__device__ float g_ao[Mrows * Emb];           // attention out [B*N, E]

// pack two floats -> half2 in a uint (RNE), pure scalar ops
__device__ __forceinline__ unsigned pack2(float lo, float hi) {
    unsigned ul = (unsigned)__half_as_ushort(__float2half_rn(lo));
    unsigned uh = (unsigned)__half_as_ushort(__float2half_rn(hi));
    return ul | (uh << 16);
}

// ---------------------------------------------------------------------------
// fp16 m16n8k16 mma macros (named float4/uint4 operands only)
// ---------------------------------------------------------------------------
#define MMA1(mt, nt)                                                          \
    asm volatile(                                                             \
        "mma.sync.aligned.m16n8k16.row.col.f32.f16.f16.f32 "                  \
        "{%0,%1,%2,%3}, {%4,%5,%6,%7}, {%8,%9}, {%0,%1,%2,%3};\n"             \
        : "+f"(c##mt##nt.x), "+f"(c##mt##nt.y),                               \
          "+f"(c##mt##nt.z), "+f"(c##mt##nt.w)                                \
        : "r"(a##mt.x), "r"(a##mt.y), "r"(a##mt.z), "r"(a##mt.w),             \
          "r"(b##nt.x), "r"(b##nt.y))

// A frag: As2u[m][k2] packed k-pairs; pairs (kk2+tig) and (kk2+tig+4)
#define LDA(mt)                                                               \
    uint4 a##mt;                                                              \
    {                                                                         \
        const int r_ = wm + mt * 16 + g;                                      \
        a##mt.x = As2u[bufc][r_][kk2 + tig];                                  \
        a##mt.y = As2u[bufc][r_ + 8][kk2 + tig];                              \
        a##mt.z = As2u[bufc][r_][kk2 + tig + 4];                              \
        a##mt.w = As2u[bufc][r_ + 8][kk2 + tig + 4];                          \
    }

// B frag: Bsu[k2][n] packed k-pairs for column n
#define LDB(nt)                                                               \
    uint2 b##nt;                                                              \
    {                                                                         \
        const int col_ = wn + nt * 8 + g;                                     \
        b##nt.x = Bsu[bufc][kk2 + tig][col_];                                 \
        b##nt.y = Bsu[bufc][kk2 + tig + 4][col_];                             \
    }

#define DEF_C(mt)                                                             \
    float4 c##mt##0 = {0.f,0.f,0.f,0.f}, c##mt##1 = {0.f,0.f,0.f,0.f},        \
           c##mt##2 = {0.f,0.f,0.f,0.f}, c##mt##3 = {0.f,0.f,0.f,0.f};

__device__ __forceinline__ void qkv_store(int row, int col, float v) {
    const int part = col >> 10;           // 0=q,1=k,2=v
    const int h    = (col >> 6) & (Hh - 1);
    const int d    = col & (Dd - 1);
    const int bb   = row >> 11;
    const int tok  = row & (Nseq - 1);
    float* dst = (part == 0) ? g_q : ((part == 1) ? g_k : g_v);
    dst[(((bb * Hh + h) * Nseq) + tok) * Dd + d] = v;
}

#define EPIQ(mt, nt)                                                          \
    {                                                                         \
        const int row_ = m0 + wm + mt * 16 + g;                               \
        const int col_ = n0 + wn + nt * 8 + 2 * tig;                          \
        qkv_store(row_,     col_,     c##mt##nt.x + bias[col_]);              \
        qkv_store(row_,     col_ + 1, c##mt##nt.y + bias[col_ + 1]);          \
        qkv_store(row_ + 8, col_,     c##mt##nt.z + bias[col_]);              \
        qkv_store(row_ + 8, col_ + 1, c##mt##nt.w + bias[col_ + 1]);          \
    }

#define EPIP(mt, nt)                                                          \
    {                                                                         \
        const int row_ = m0 + wm + mt * 16 + g;                               \
        const int col_ = n0 + wn + nt * 8 + 2 * tig;                          \
        out[row_ * Emb + col_]           = c##mt##nt.x + bias[col_];          \
        out[row_ * Emb + col_ + 1]       = c##mt##nt.y + bias[col_ + 1];      \
        out[(row_ + 8) * Emb + col_]     = c##mt##nt.z + bias[col_];          \
        out[(row_ + 8) * Emb + col_ + 1] = c##mt##nt.w + bias[col_ + 1];      \
    }

#define GEMM_IDX                                                              \
    const int tid  = threadIdx.x;                                             \
    const int lane = tid & 31;                                                \
    const int w    = tid >> 5;                                                \
    const int g    = lane >> 2;                                               \
    const int tig  = lane & 3;                                                \
    const int wm   = (w >> 2) * 64;                                           \
    const int wn   = (w & 3) * 32;                                            \
    const int m0   = blockIdx.y * 128;                                        \
    const int n0   = blockIdx.x * 128;                                        \
    const int am   = tid >> 4;    /* A stage: rows am+16j, pair ak2 */        \
    const int ak2  = tid & 15;                                                \
    const int bn   = tid & 127;   /* B stage: col bn, pairs bq+2j  */         \
    const int bq   = tid >> 7;

// staging loads (AEL/BEL defined per kernel), stores, 8 each
#define LGA(j, koff) pa##j = pack2(AEL(am + 16*(j), (koff) + 2*ak2),          \
                                   AEL(am + 16*(j), (koff) + 2*ak2 + 1));
#define LGB(j, koff) pb##j = pack2(BEL((koff) + 2*(bq + 2*(j)), bn),          \
                                   BEL((koff) + 2*(bq + 2*(j)) + 1, bn));
#define LG8(koff) LGA(0,koff) LGA(1,koff) LGA(2,koff) LGA(3,koff)             \
                  LGA(4,koff) LGA(5,koff) LGA(6,koff) LGA(7,koff)             \
                  LGB(0,koff) LGB(1,koff) LGB(2,koff) LGB(3,koff)             \
                  LGB(4,koff) LGB(5,koff) LGB(6,koff) LGB(7,koff)
#define STA(j, bf) As2u[bf][am + 16*(j)][ak2] = pa##j;
#define STB(j, bf) Bsu[bf][bq + 2*(j)][bn] = pb##j;
#define ST8(bf) STA(0,bf) STA(1,bf) STA(2,bf) STA(3,bf)                       \
                STA(4,bf) STA(5,bf) STA(6,bf) STA(7,bf)                       \
                STB(0,bf) STB(1,bf) STB(2,bf) STB(3,bf)                       \
                STB(4,bf) STB(5,bf) STB(6,bf) STB(7,bf)

// double-buffered fp16 GEMM mainloop (block 128x128, k-chunk 32)
#define GEMM_MAIN_BODY                                                        \
    __shared__ unsigned As2u[2][128][20];                                     \
    __shared__ unsigned Bsu[2][16][136];                                      \
    GEMM_IDX                                                                  \
    DEF_C(0) DEF_C(1) DEF_C(2) DEF_C(3)                                       \
    unsigned pa0,pa1,pa2,pa3,pa4,pa5,pa6,pa7;                                 \
    unsigned pb0,pb1,pb2,pb3,pb4,pb5,pb6,pb7;                                 \
    LG8(0)                                                                    \
    ST8(0)                                                                    \
    __syncthreads();                                                          \
    for (int k0 = 0; k0 < Emb; k0 += 32) {                                    \
        const int bufc = (k0 >> 5) & 1;                                       \
        const bool more = (k0 + 32 < Emb);                                    \
        if (more) { LG8(k0 + 32) }                                            \
        _Pragma("unroll")                                                     \
        for (int ks = 0; ks < 2; ks++) {                                      \
            const int kk2 = ks * 8;                                           \
            LDA(0) LDA(1) LDA(2) LDA(3)                                       \
            LDB(0) LDB(1) LDB(2) LDB(3)                                       \
            MMA1(0,0); MMA1(0,1); MMA1(0,2); MMA1(0,3);                       \
            MMA1(1,0); MMA1(1,1); MMA1(1,2); MMA1(1,3);                       \
            MMA1(2,0); MMA1(2,1); MMA1(2,2); MMA1(2,3);                       \
            MMA1(3,0); MMA1(3,1); MMA1(3,2); MMA1(3,3);                       \
        }                                                                     \
        if (more) { const int nb = bufc ^ 1; ST8(nb) }                        \
        __syncthreads();                                                      \
    }

// ---------------------------------------------------------------------------
// QKV GEMM: X[4096,1024] @ Wq[1024,3072] + bias -> scatter q/k/v
// ---------------------------------------------------------------------------
__global__ __launch_bounds__(256) void qkv_hmma(
    const float* __restrict__ X, const float* __restrict__ Wq,
    const float* __restrict__ bias)
{
#define AEL(mr, kc) X[(m0 + (mr)) * Emb + (kc)]
#define BEL(kr, nc) Wq[(kr) * E3 + n0 + (nc)]
    GEMM_MAIN_BODY
#undef AEL
#undef BEL
    EPIQ(0,0) EPIQ(0,1) EPIQ(0,2) EPIQ(0,3)
    EPIQ(1,0) EPIQ(1,1) EPIQ(1,2) EPIQ(1,3)
    EPIQ(2,0) EPIQ(2,1) EPIQ(2,2) EPIQ(2,3)
    EPIQ(3,0) EPIQ(3,1) EPIQ(3,2) EPIQ(3,3)
}

// ---------------------------------------------------------------------------
// Output projection: g_ao[4096,1024] @ Wp[1024,1024] + bias -> d_out
// ---------------------------------------------------------------------------
__global__ __launch_bounds__(256) void proj_hmma(
    const float* __restrict__ Wp, const float* __restrict__ bias,
    float* __restrict__ out)
{
#define AEL(mr, kc) g_ao[(m0 + (mr)) * Emb + (kc)]
#define BEL(kr, nc) Wp[(kr) * Emb + n0 + (nc)]
    GEMM_MAIN_BODY
#undef AEL
#undef BEL
    EPIP(0,0) EPIP(0,1) EPIP(0,2) EPIP(0,3)
    EPIP(1,0) EPIP(1,1) EPIP(1,2) EPIP(1,3)
    EPIP(2,0) EPIP(2,1) EPIP(2,2) EPIP(2,3)
    EPIP(3,0) EPIP(3,1) EPIP(3,2) EPIP(3,3)
}

// ---------------------------------------------------------------------------
// Flash attention, fp16 mma. Block = 64 queries x (b,h); 4 warps x 16 queries.
// Q/K/V smem: packed d-pairs [token][d2] (stride 36 uint). P stays in
// registers: S C-frags repack directly into PV A-frags. V key-pair B-frags
// assembled with one byte_perm per reg.
// ---------------------------------------------------------------------------
#define MMA_S(nt)                                                             \
    {                                                                         \
        const unsigned bx = Ksu[nt * 8 + g][kk2 + tig];                       \
        const unsigned by = Ksu[nt * 8 + g][kk2 + tig + 4];                   \
        asm volatile(                                                         \
            "mma.sync.aligned.m16n8k16.row.col.f32.f16.f16.f32 "              \
            "{%0,%1,%2,%3}, {%4,%5,%6,%7}, {%8,%9}, {%0,%1,%2,%3};\n"         \
            : "+f"(s##nt.x), "+f"(s##nt.y), "+f"(s##nt.z), "+f"(s##nt.w)      \
            : "r"(a0), "r"(a1), "r"(a2), "r"(a3), "r"(bx), "r"(by));          \
    }

#define MMA_OV(nt)                                                            \
    {                                                                         \
        const int d2_ = nt * 4 + (g >> 1);                                    \
        const unsigned bx = __byte_perm(Vsu[kp0][d2_],     Vsu[kp0+1][d2_], psel); \
        const unsigned by = __byte_perm(Vsu[kp0+8][d2_],   Vsu[kp0+9][d2_], psel); \
        asm volatile(                                                         \
            "mma.sync.aligned.m16n8k16.row.col.f32.f16.f16.f32 "              \
            "{%0,%1,%2,%3}, {%4,%5,%6,%7}, {%8,%9}, {%0,%1,%2,%3};\n"         \
            : "+f"(o##nt.x), "+f"(o##nt.y), "+f"(o##nt.z), "+f"(o##nt.w)      \
            : "r"(a0), "r"(a1), "r"(a2), "r"(a3), "r"(bx), "r"(by));          \
    }

#define PVSTEP(kt, sa, sb)                                                    \
    {                                                                         \
        const unsigned a0 = pack2(sa.x, sa.y);                                \
        const unsigned a1 = pack2(sa.z, sa.w);                                \
        const unsigned a2 = pack2(sb.x, sb.y);                                \
        const unsigned a3 = pack2(sb.z, sb.w);                                \
        const int kp0 = (kt) * 16 + 2 * tig;                                  \
        MMA_OV(0) MMA_OV(1) MMA_OV(2) MMA_OV(3)                               \
        MMA_OV(4) MMA_OV(5) MMA_OV(6) MMA_OV(7)                               \
    }

#define SMAX(nt)                                                              \
    { s##nt.x *= 0.125f; s##nt.y *= 0.125f; s##nt.z *= 0.125f; s##nt.w *= 0.125f; \
      mx0 = fmaxf(mx0, fmaxf(s##nt.x, s##nt.y));                              \
      mx1 = fmaxf(mx1, fmaxf(s##nt.z, s##nt.w)); }

#define SEXP(nt)                                                              \
    { s##nt.x = __expf(s##nt.x - nm0); s##nt.y = __expf(s##nt.y - nm0);       \
      s##nt.z = __expf(s##nt.z - nm1); s##nt.w = __expf(s##nt.w - nm1);       \
      sum0 += s##nt.x + s##nt.y; sum1 += s##nt.z + s##nt.w; }

#define OCORR(nt)                                                             \
    { o##nt.x *= corr0; o##nt.y *= corr0; o##nt.z *= corr1; o##nt.w *= corr1; }

#define OSTORE(nt)                                                            \
    { const int cc = nt * 8 + 2 * tig;                                        \
      dst0[cc]     = o##nt.x * inv0;                                          \
      dst0[cc + 1] = o##nt.y * inv0;                                          \
      dst1[cc]     = o##nt.z * inv1;                                          \
      dst1[cc + 1] = o##nt.w * inv1; }

__global__ __launch_bounds__(128) void attn_hmma()
{
    __shared__ unsigned Qsu[64][36];   // [q][d2]
    __shared__ unsigned Ksu[64][36];   // [key][d2]
    __shared__ unsigned Vsu[64][36];   // [key][d2]

    const int tid  = threadIdx.x;
    const int lane = tid & 31;
    const int w    = tid >> 5;          // warp -> queries [16w,16w+16)
    const int g    = lane >> 2;
    const int tig  = lane & 3;
    const int bh   = blockIdx.y;
    const int q0   = blockIdx.x * 64;
    const int qr   = w * 16 + g;
    const unsigned psel = (g & 1) ? 0x7632u : 0x5410u;

    const float* Qg = g_q + (size_t)(bh * Nseq + q0) * Dd;
    const float* Kg = g_k + (size_t)bh * Nseq * Dd;
    const float* Vg = g_v + (size_t)bh * Nseq * Dd;

    #pragma unroll
    for (int u = 0; u < 16; u++) {
        const int e = tid + u * 128;
        const int q = e >> 5, d2 = e & 31;
        Qsu[q][d2] = pack2(Qg[q * 64 + 2 * d2], Qg[q * 64 + 2 * d2 + 1]);
    }

    float m0r = -INFINITY, m1r = -INFINITY, l0 = 0.0f, l1 = 0.0f;
    float4 o0 = {0.f,0.f,0.f,0.f}, o1 = {0.f,0.f,0.f,0.f},
           o2 = {0.f,0.f,0.f,0.f}, o3 = {0.f,0.f,0.f,0.f},
           o4 = {0.f,0.f,0.f,0.f}, o5 = {0.f,0.f,0.f,0.f},
           o6 = {0.f,0.f,0.f,0.f}, o7 = {0.f,0.f,0.f,0.f};
    __syncthreads();

    for (int t = 0; t < Nseq / 64; t++) {
        const float* Kt = Kg + t * 64 * Dd;
        const float* Vt = Vg + t * 64 * Dd;
        #pragma unroll
        for (int u = 0; u < 16; u++) {
            const int e = tid + u * 128;
            const int r = e >> 5, d2 = e & 31;
            Ksu[r][d2] = pack2(Kt[r * 64 + 2 * d2], Kt[r * 64 + 2 * d2 + 1]);
            Vsu[r][d2] = pack2(Vt[r * 64 + 2 * d2], Vt[r * 64 + 2 * d2 + 1]);
        }
        __syncthreads();

        // S = Q @ K^T  (16q x 64key per warp, k=64 over 4 mma-K steps)
        float4 s0 = {0.f,0.f,0.f,0.f}, s1 = {0.f,0.f,0.f,0.f},
               s2 = {0.f,0.f,0.f,0.f}, s3 = {0.f,0.f,0.f,0.f},
               s4 = {0.f,0.f,0.f,0.f}, s5 = {0.f,0.f,0.f,0.f},
               s6 = {0.f,0.f,0.f,0.f}, s7 = {0.f,0.f,0.f,0.f};
        #pragma unroll
        for (int ks = 0; ks < 4; ks++) {
            const int kk2 = ks * 8;
            const unsigned a0 = Qsu[qr][kk2 + tig];
            const unsigned a1 = Qsu[qr + 8][kk2 + tig];
            const unsigned a2 = Qsu[qr][kk2 + tig + 4];
            const unsigned a3 = Qsu[qr + 8][kk2 + tig + 4];
            MMA_S(0) MMA_S(1) MMA_S(2) MMA_S(3)
            MMA_S(4) MMA_S(5) MMA_S(6) MMA_S(7)
        }

        // online softmax (rows qr, qr+8; reduce over tig via shfl 1,2)
        float mx0 = -INFINITY, mx1 = -INFINITY;
        SMAX(0) SMAX(1) SMAX(2) SMAX(3) SMAX(4) SMAX(5) SMAX(6) SMAX(7)
        mx0 = fmaxf(mx0, __shfl_xor_sync(0xffffffffu, mx0, 1));
        mx0 = fmaxf(mx0, __shfl_xor_sync(0xffffffffu, mx0, 2));
        mx1 = fmaxf(mx1, __shfl_xor_sync(0xffffffffu, mx1, 1));
        mx1 = fmaxf(mx1, __shfl_xor_sync(0xffffffffu, mx1, 2));
        const float nm0 = fmaxf(m0r, mx0);
        const float nm1 = fmaxf(m1r, mx1);
        float sum0 = 0.0f, sum1 = 0.0f;
        SEXP(0) SEXP(1) SEXP(2) SEXP(3) SEXP(4) SEXP(5) SEXP(6) SEXP(7)
        sum0 += __shfl_xor_sync(0xffffffffu, sum0, 1);
        sum0 += __shfl_xor_sync(0xffffffffu, sum0, 2);
        sum1 += __shfl_xor_sync(0xffffffffu, sum1, 1);
        sum1 += __shfl_xor_sync(0xffffffffu, sum1, 2);
        const float corr0 = __expf(m0r - nm0);   // exp(-inf)=0 first iter
        const float corr1 = __expf(m1r - nm1);
        l0 = l0 * corr0 + sum0;
        l1 = l1 * corr1 + sum1;
        m0r = nm0; m1r = nm1;
        OCORR(0) OCORR(1) OCORR(2) OCORR(3) OCORR(4) OCORR(5) OCORR(6) OCORR(7)

        // O += P @ V  — P passed register-to-register from S C-frags
        PVSTEP(0, s0, s1)
        PVSTEP(1, s2, s3)
        PVSTEP(2, s4, s5)
        PVSTEP(3, s6, s7)
        __syncthreads();
    }

    // epilogue: normalize + write [B,N,H*D] (scalar stores)
    const int bb = bh >> 4;
    const int h  = bh & (Hh - 1);
    const float inv0 = 1.0f / l0;
    const float inv1 = 1.0f / l1;
    const int row0 = q0 + qr;
    float* dst0 = &g_ao[(size_t)(bb * Nseq + row0) * Emb + h * Dd];
    float* dst1 = &g_ao[(size_t)(bb * Nseq + row0 + 8) * Emb + h * Dd];
    OSTORE(0) OSTORE(1) OSTORE(2) OSTORE(3)
    OSTORE(4) OSTORE(5) OSTORE(6) OSTORE(7)
}

// ---------------------------------------------------------------------------
extern "C" void kernel_launch(void* const* d_in, const int* in_sizes, int n_in,
                              void* d_out, int out_size)
{
    const float* x      = (const float*)d_in[0];
    const float* w_qkv  = (const float*)d_in[1];
    const float* b_qkv  = (const float*)d_in[2];
    const float* w_proj = (const float*)d_in[3];
    const float* b_proj = (const float*)d_in[4];
    float* out = (float*)d_out;

    qkv_hmma<<<dim3(E3 / 128, Mrows / 128), 256>>>(x, w_qkv, b_qkv);
    attn_hmma<<<dim3(Nseq / 64, Bsz * Hh), 128>>>();
    proj_hmma<<<dim3(Emb / 128, Mrows / 128), 256>>>(w_proj, b_proj, out);
}

// round 13
// speedup vs baseline: 5.7261x; 1.4307x over previous
#include <cuda_runtime.h>
#include <cuda_fp16.h>
#include <math.h>

#define Bsz  2
#define Nseq 2048
#define Emb  1024
#define Hh   16
#define Dd   64
#define Mrows 4096
#define E3   3072
#define Emb2 512          // Emb/2  (packed pairs)
#define D2   32           // Dd/2

// Packed half2-in-uint scratch (scalar 32-bit access only — safe envelope).
__device__ unsigned g_xh[Mrows * Emb2];          // x packed along E
__device__ unsigned g_wqh[Emb2 * E3];            // w_qkv packed along k (rows)
__device__ unsigned g_wph[Emb2 * Emb];           // w_proj packed along k
__device__ unsigned g_qh[Bsz * Hh * Nseq * D2];  // [B,H,N,D/2]
__device__ unsigned g_kh[Bsz * Hh * Nseq * D2];
__device__ unsigned g_vh[Bsz * Hh * Nseq * D2];
__device__ unsigned g_aoh[Mrows * Emb2];         // attention out packed [B*N, E/2]

__device__ __forceinline__ unsigned pack2(float lo, float hi) {
    unsigned ul = (unsigned)__half_as_ushort(__float2half_rn(lo));
    unsigned uh = (unsigned)__half_as_ushort(__float2half_rn(hi));
    return ul | (uh << 16);
}

// ---------------------------------------------------------------------------
// Prep kernels: pack fp32 inputs to half2 uints ONCE per launch.
// ---------------------------------------------------------------------------
__global__ __launch_bounds__(256) void pack_x_kernel(const float* __restrict__ x)
{
    const int i = blockIdx.x * 256 + threadIdx.x;       // 0..Mrows*Emb2-1
    g_xh[i] = pack2(x[2 * i], x[2 * i + 1]);            // adjacent-pair pack
}

__global__ __launch_bounds__(256) void pack_wq_kernel(const float* __restrict__ w)
{
    const int i = blockIdx.x * 256 + threadIdx.x;       // 0..Emb2*E3-1
    const int k2 = i / E3;
    const int n  = i - k2 * E3;
    g_wqh[i] = pack2(w[k2 * (2 * E3) + n], w[k2 * (2 * E3) + E3 + n]);
}

__global__ __launch_bounds__(256) void pack_wp_kernel(const float* __restrict__ w)
{
    const int i = blockIdx.x * 256 + threadIdx.x;       // 0..Emb2*Emb-1
    const int k2 = i >> 10;
    const int n  = i & (Emb - 1);
    g_wph[i] = pack2(w[k2 * (2 * Emb) + n], w[k2 * (2 * Emb) + Emb + n]);
}

// ---------------------------------------------------------------------------
// fp16 m16n8k16 mma macros (verified R12 fragment maps, unchanged)
// ---------------------------------------------------------------------------
#define MMA1(mt, nt)                                                          \
    asm volatile(                                                             \
        "mma.sync.aligned.m16n8k16.row.col.f32.f16.f16.f32 "                  \
        "{%0,%1,%2,%3}, {%4,%5,%6,%7}, {%8,%9}, {%0,%1,%2,%3};\n"             \
        : "+f"(c##mt##nt.x), "+f"(c##mt##nt.y),                               \
          "+f"(c##mt##nt.z), "+f"(c##mt##nt.w)                                \
        : "r"(a##mt.x), "r"(a##mt.y), "r"(a##mt.z), "r"(a##mt.w),             \
          "r"(b##nt.x), "r"(b##nt.y))

#define LDA(mt)                                                               \
    uint4 a##mt;                                                              \
    {                                                                         \
        const int r_ = wm + mt * 16 + g;                                      \
        a##mt.x = As2u[bufc][r_][kk2 + tig];                                  \
        a##mt.y = As2u[bufc][r_ + 8][kk2 + tig];                              \
        a##mt.z = As2u[bufc][r_][kk2 + tig + 4];                              \
        a##mt.w = As2u[bufc][r_ + 8][kk2 + tig + 4];                          \
    }

#define LDB(nt)                                                               \
    uint2 b##nt;                                                              \
    {                                                                         \
        const int col_ = wn + nt * 8 + g;                                     \
        b##nt.x = Bsu[bufc][kk2 + tig][col_];                                 \
        b##nt.y = Bsu[bufc][kk2 + tig + 4][col_];                             \
    }

#define DEF_C(mt)                                                             \
    float4 c##mt##0 = {0.f,0.f,0.f,0.f}, c##mt##1 = {0.f,0.f,0.f,0.f},        \
           c##mt##2 = {0.f,0.f,0.f,0.f}, c##mt##3 = {0.f,0.f,0.f,0.f};

// qkv epilogue: packed store of an adjacent column pair
__device__ __forceinline__ void qkv_store2(int row, int col, float v0, float v1) {
    const int part = col >> 10;           // 0=q,1=k,2=v
    const int h    = (col >> 6) & (Hh - 1);
    const int d2   = (col & (Dd - 1)) >> 1;
    const int bb   = row >> 11;
    const int tok  = row & (Nseq - 1);
    unsigned* dst = (part == 0) ? g_qh : ((part == 1) ? g_kh : g_vh);
    dst[(((bb * Hh + h) * Nseq) + tok) * D2 + d2] = pack2(v0, v1);
}

#define EPIQ(mt, nt)                                                          \
    {                                                                         \
        const int row_ = m0 + wm + mt * 16 + g;                               \
        const int col_ = n0 + wn + nt * 8 + 2 * tig;                          \
        qkv_store2(row_,     col_, c##mt##nt.x + bias[col_], c##mt##nt.y + bias[col_ + 1]); \
        qkv_store2(row_ + 8, col_, c##mt##nt.z + bias[col_], c##mt##nt.w + bias[col_ + 1]); \
    }

#define EPIP(mt, nt)                                                          \
    {                                                                         \
        const int row_ = m0 + wm + mt * 16 + g;                               \
        const int col_ = n0 + wn + nt * 8 + 2 * tig;                          \
        out[row_ * Emb + col_]           = c##mt##nt.x + bias[col_];          \
        out[row_ * Emb + col_ + 1]       = c##mt##nt.y + bias[col_ + 1];      \
        out[(row_ + 8) * Emb + col_]     = c##mt##nt.z + bias[col_];          \
        out[(row_ + 8) * Emb + col_ + 1] = c##mt##nt.w + bias[col_ + 1];      \
    }

#define GEMM_IDX                                                              \
    const int tid  = threadIdx.x;                                             \
    const int lane = tid & 31;                                                \
    const int w    = tid >> 5;                                                \
    const int g    = lane >> 2;                                               \
    const int tig  = lane & 3;                                                \
    const int wm   = (w >> 2) * 64;                                           \
    const int wn   = (w & 3) * 32;                                            \
    const int m0   = blockIdx.y * 128;                                        \
    const int n0   = blockIdx.x * 128;                                        \
    const int am   = tid >> 4;    /* A stage: rows am+16j, pair ak2 */        \
    const int ak2  = tid & 15;                                                \
    const int bn   = tid & 127;   /* B stage: col bn, pair rows bq+2j */      \
    const int bq   = tid >> 7;

// packed staging: ONE uint LDG per 2 elements, zero conversion
#define LGA(j, koff2) pa##j = AELU(am + 16*(j), (koff2) + ak2);
#define LGB(j, koff2) pb##j = BELU((koff2) + bq + 2*(j), bn);
#define LG8(koff2) LGA(0,koff2) LGA(1,koff2) LGA(2,koff2) LGA(3,koff2)        \
                   LGA(4,koff2) LGA(5,koff2) LGA(6,koff2) LGA(7,koff2)        \
                   LGB(0,koff2) LGB(1,koff2) LGB(2,koff2) LGB(3,koff2)        \
                   LGB(4,koff2) LGB(5,koff2) LGB(6,koff2) LGB(7,koff2)
#define STA(j, bf) As2u[bf][am + 16*(j)][ak2] = pa##j;
#define STB(j, bf) Bsu[bf][bq + 2*(j)][bn] = pb##j;
#define ST8(bf) STA(0,bf) STA(1,bf) STA(2,bf) STA(3,bf)                       \
                STA(4,bf) STA(5,bf) STA(6,bf) STA(7,bf)                       \
                STB(0,bf) STB(1,bf) STB(2,bf) STB(3,bf)                       \
                STB(4,bf) STB(5,bf) STB(6,bf) STB(7,bf)

// double-buffered fp16 GEMM mainloop (block 128x128, k-chunk 32 = 16 pairs)
#define GEMM_MAIN_BODY                                                        \
    __shared__ unsigned As2u[2][128][20];                                     \
    __shared__ unsigned Bsu[2][16][136];                                      \
    GEMM_IDX                                                                  \
    DEF_C(0) DEF_C(1) DEF_C(2) DEF_C(3)                                       \
    unsigned pa0,pa1,pa2,pa3,pa4,pa5,pa6,pa7;                                 \
    unsigned pb0,pb1,pb2,pb3,pb4,pb5,pb6,pb7;                                 \
    LG8(0)                                                                    \
    ST8(0)                                                                    \
    __syncthreads();                                                          \
    for (int k2c = 0; k2c < Emb2; k2c += 16) {                                \
        const int bufc = (k2c >> 4) & 1;                                      \
        const bool more = (k2c + 16 < Emb2);                                  \
        if (more) { LG8(k2c + 16) }                                           \
        _Pragma("unroll")                                                     \
        for (int ks = 0; ks < 2; ks++) {                                      \
            const int kk2 = ks * 8;                                           \
            LDA(0) LDA(1) LDA(2) LDA(3)                                       \
            LDB(0) LDB(1) LDB(2) LDB(3)                                       \
            MMA1(0,0); MMA1(0,1); MMA1(0,2); MMA1(0,3);                       \
            MMA1(1,0); MMA1(1,1); MMA1(1,2); MMA1(1,3);                       \
            MMA1(2,0); MMA1(2,1); MMA1(2,2); MMA1(2,3);                       \
            MMA1(3,0); MMA1(3,1); MMA1(3,2); MMA1(3,3);                       \
        }                                                                     \
        if (more) { const int nb = bufc ^ 1; ST8(nb) }                        \
        __syncthreads();                                                      \
    }

// ---------------------------------------------------------------------------
// QKV GEMM: xh[4096,512] @ wqh[512,3072] + bias -> packed q/k/v
// ---------------------------------------------------------------------------
__global__ __launch_bounds__(256) void qkv_hmma(const float* __restrict__ bias)
{
#define AELU(mr, kc2) g_xh[(m0 + (mr)) * Emb2 + (kc2)]
#define BELU(kr2, nc) g_wqh[(kr2) * E3 + n0 + (nc)]
    GEMM_MAIN_BODY
#undef AELU
#undef BELU
    EPIQ(0,0) EPIQ(0,1) EPIQ(0,2) EPIQ(0,3)
    EPIQ(1,0) EPIQ(1,1) EPIQ(1,2) EPIQ(1,3)
    EPIQ(2,0) EPIQ(2,1) EPIQ(2,2) EPIQ(2,3)
    EPIQ(3,0) EPIQ(3,1) EPIQ(3,2) EPIQ(3,3)
}

// ---------------------------------------------------------------------------
// Output projection: aoh[4096,512] @ wph[512,1024] + bias -> d_out (fp32)
// ---------------------------------------------------------------------------
__global__ __launch_bounds__(256) void proj_hmma(
    const float* __restrict__ bias, float* __restrict__ out)
{
#define AELU(mr, kc2) g_aoh[(m0 + (mr)) * Emb2 + (kc2)]
#define BELU(kr2, nc) g_wph[(kr2) * Emb + n0 + (nc)]
    GEMM_MAIN_BODY
#undef AELU
#undef BELU
    EPIP(0,0) EPIP(0,1) EPIP(0,2) EPIP(0,3)
    EPIP(1,0) EPIP(1,1) EPIP(1,2) EPIP(1,3)
    EPIP(2,0) EPIP(2,1) EPIP(2,2) EPIP(2,3)
    EPIP(3,0) EPIP(3,1) EPIP(3,2) EPIP(3,3)
}

// ---------------------------------------------------------------------------
// Flash attention, fp16 mma (verified R12 structure; packed global I/O).
// ---------------------------------------------------------------------------
#define MMA_S(nt)                                                             \
    {                                                                         \
        const unsigned bx = Ksu[nt * 8 + g][kk2 + tig];                       \
        const unsigned by = Ksu[nt * 8 + g][kk2 + tig + 4];                   \
        asm volatile(                                                         \
            "mma.sync.aligned.m16n8k16.row.col.f32.f16.f16.f32 "              \
            "{%0,%1,%2,%3}, {%4,%5,%6,%7}, {%8,%9}, {%0,%1,%2,%3};\n"         \
            : "+f"(s##nt.x), "+f"(s##nt.y), "+f"(s##nt.z), "+f"(s##nt.w)      \
            : "r"(a0), "r"(a1), "r"(a2), "r"(a3), "r"(bx), "r"(by));          \
    }

#define MMA_OV(nt)                                                            \
    {                                                                         \
        const int d2_ = nt * 4 + (g >> 1);                                    \
        const unsigned bx = __byte_perm(Vsu[kp0][d2_],   Vsu[kp0+1][d2_], psel); \
        const unsigned by = __byte_perm(Vsu[kp0+8][d2_], Vsu[kp0+9][d2_], psel); \
        asm volatile(                                                         \
            "mma.sync.aligned.m16n8k16.row.col.f32.f16.f16.f32 "              \
            "{%0,%1,%2,%3}, {%4,%5,%6,%7}, {%8,%9}, {%0,%1,%2,%3};\n"         \
            : "+f"(o##nt.x), "+f"(o##nt.y), "+f"(o##nt.z), "+f"(o##nt.w)      \
            : "r"(a0), "r"(a1), "r"(a2), "r"(a3), "r"(bx), "r"(by));          \
    }

#define PVSTEP(kt, sa, sb)                                                    \
    {                                                                         \
        const unsigned a0 = pack2(sa.x, sa.y);                                \
        const unsigned a1 = pack2(sa.z, sa.w);                                \
        const unsigned a2 = pack2(sb.x, sb.y);                                \
        const unsigned a3 = pack2(sb.z, sb.w);                                \
        const int kp0 = (kt) * 16 + 2 * tig;                                  \
        MMA_OV(0) MMA_OV(1) MMA_OV(2) MMA_OV(3)                               \
        MMA_OV(4) MMA_OV(5) MMA_OV(6) MMA_OV(7)                               \
    }

#define SMAX(nt)                                                              \
    { s##nt.x *= 0.125f; s##nt.y *= 0.125f; s##nt.z *= 0.125f; s##nt.w *= 0.125f; \
      mx0 = fmaxf(mx0, fmaxf(s##nt.x, s##nt.y));                              \
      mx1 = fmaxf(mx1, fmaxf(s##nt.z, s##nt.w)); }

#define SEXP(nt)                                                              \
    { s##nt.x = __expf(s##nt.x - nm0); s##nt.y = __expf(s##nt.y - nm0);       \
      s##nt.z = __expf(s##nt.z - nm1); s##nt.w = __expf(s##nt.w - nm1);       \
      sum0 += s##nt.x + s##nt.y; sum1 += s##nt.z + s##nt.w; }

#define OCORR(nt)                                                             \
    { o##nt.x *= corr0; o##nt.y *= corr0; o##nt.z *= corr1; o##nt.w *= corr1; }

#define OSTORE(nt)                                                            \
    { dst0[nt * 4 + tig] = pack2(o##nt.x * inv0, o##nt.y * inv0);             \
      dst1[nt * 4 + tig] = pack2(o##nt.z * inv1, o##nt.w * inv1); }

__global__ __launch_bounds__(128) void attn_hmma()
{
    __shared__ unsigned Qsu[64][36];   // [q][d2]
    __shared__ unsigned Ksu[64][36];   // [key][d2]
    __shared__ unsigned Vsu[64][36];   // [key][d2]

    const int tid  = threadIdx.x;
    const int lane = tid & 31;
    const int w    = tid >> 5;          // warp -> queries [16w,16w+16)
    const int g    = lane >> 2;
    const int tig  = lane & 3;
    const int bh   = blockIdx.y;
    const int q0   = blockIdx.x * 64;
    const int qr   = w * 16 + g;
    const unsigned psel = (g & 1) ? 0x7632u : 0x5410u;

    const unsigned* Qg = g_qh + (size_t)(bh * Nseq + q0) * D2;
    const unsigned* Kg = g_kh + (size_t)bh * Nseq * D2;
    const unsigned* Vg = g_vh + (size_t)bh * Nseq * D2;

    #pragma unroll
    for (int u = 0; u < 16; u++) {
        const int e = tid + u * 128;
        Qsu[e >> 5][e & 31] = Qg[e];    // packed pass-through
    }

    float m0r = -INFINITY, m1r = -INFINITY, l0 = 0.0f, l1 = 0.0f;
    float4 o0 = {0.f,0.f,0.f,0.f}, o1 = {0.f,0.f,0.f,0.f},
           o2 = {0.f,0.f,0.f,0.f}, o3 = {0.f,0.f,0.f,0.f},
           o4 = {0.f,0.f,0.f,0.f}, o5 = {0.f,0.f,0.f,0.f},
           o6 = {0.f,0.f,0.f,0.f}, o7 = {0.f,0.f,0.f,0.f};
    __syncthreads();

    for (int t = 0; t < Nseq / 64; t++) {
        const unsigned* Kt = Kg + t * 64 * D2;
        const unsigned* Vt = Vg + t * 64 * D2;
        #pragma unroll
        for (int u = 0; u < 16; u++) {
            const int e = tid + u * 128;
            const int r = e >> 5, d2 = e & 31;
            Ksu[r][d2] = Kt[e];
            Vsu[r][d2] = Vt[e];
        }
        __syncthreads();

        float4 s0 = {0.f,0.f,0.f,0.f}, s1 = {0.f,0.f,0.f,0.f},
               s2 = {0.f,0.f,0.f,0.f}, s3 = {0.f,0.f,0.f,0.f},
               s4 = {0.f,0.f,0.f,0.f}, s5 = {0.f,0.f,0.f,0.f},
               s6 = {0.f,0.f,0.f,0.f}, s7 = {0.f,0.f,0.f,0.f};
        #pragma unroll
        for (int ks = 0; ks < 4; ks++) {
            const int kk2 = ks * 8;
            const unsigned a0 = Qsu[qr][kk2 + tig];
            const unsigned a1 = Qsu[qr + 8][kk2 + tig];
            const unsigned a2 = Qsu[qr][kk2 + tig + 4];
            const unsigned a3 = Qsu[qr + 8][kk2 + tig + 4];
            MMA_S(0) MMA_S(1) MMA_S(2) MMA_S(3)
            MMA_S(4) MMA_S(5) MMA_S(6) MMA_S(7)
        }

        float mx0 = -INFINITY, mx1 = -INFINITY;
        SMAX(0) SMAX(1) SMAX(2) SMAX(3) SMAX(4) SMAX(5) SMAX(6) SMAX(7)
        mx0 = fmaxf(mx0, __shfl_xor_sync(0xffffffffu, mx0, 1));
        mx0 = fmaxf(mx0, __shfl_xor_sync(0xffffffffu, mx0, 2));
        mx1 = fmaxf(mx1, __shfl_xor_sync(0xffffffffu, mx1, 1));
        mx1 = fmaxf(mx1, __shfl_xor_sync(0xffffffffu, mx1, 2));
        const float nm0 = fmaxf(m0r, mx0);
        const float nm1 = fmaxf(m1r, mx1);
        float sum0 = 0.0f, sum1 = 0.0f;
        SEXP(0) SEXP(1) SEXP(2) SEXP(3) SEXP(4) SEXP(5) SEXP(6) SEXP(7)
        sum0 += __shfl_xor_sync(0xffffffffu, sum0, 1);
        sum0 += __shfl_xor_sync(0xffffffffu, sum0, 2);
        sum1 += __shfl_xor_sync(0xffffffffu, sum1, 1);
        sum1 += __shfl_xor_sync(0xffffffffu, sum1, 2);
        const float corr0 = __expf(m0r - nm0);   // exp(-inf)=0 first iter
        const float corr1 = __expf(m1r - nm1);
        l0 = l0 * corr0 + sum0;
        l1 = l1 * corr1 + sum1;
        m0r = nm0; m1r = nm1;
        OCORR(0) OCORR(1) OCORR(2) OCORR(3) OCORR(4) OCORR(5) OCORR(6) OCORR(7)

        PVSTEP(0, s0, s1)
        PVSTEP(1, s2, s3)
        PVSTEP(2, s4, s5)
        PVSTEP(3, s6, s7)
        __syncthreads();
    }

    // epilogue: normalize + packed store to g_aoh [B*N, E/2]
    const int bb = bh >> 4;
    const int h  = bh & (Hh - 1);
    const float inv0 = 1.0f / l0;
    const float inv1 = 1.0f / l1;
    const int row0 = q0 + qr;
    unsigned* dst0 = &g_aoh[(size_t)(bb * Nseq + row0) * Emb2 + h * D2];
    unsigned* dst1 = &g_aoh[(size_t)(bb * Nseq + row0 + 8) * Emb2 + h * D2];
    OSTORE(0) OSTORE(1) OSTORE(2) OSTORE(3)
    OSTORE(4) OSTORE(5) OSTORE(6) OSTORE(7)
}

// ---------------------------------------------------------------------------
extern "C" void kernel_launch(void* const* d_in, const int* in_sizes, int n_in,
                              void* d_out, int out_size)
{
    const float* x      = (const float*)d_in[0];
    const float* w_qkv  = (const float*)d_in[1];
    const float* b_qkv  = (const float*)d_in[2];
    const float* w_proj = (const float*)d_in[3];
    const float* b_proj = (const float*)d_in[4];
    float* out = (float*)d_out;

    pack_x_kernel <<<(Mrows * Emb2) / 256, 256>>>(x);
    pack_wq_kernel<<<(Emb2 * E3)   / 256, 256>>>(w_qkv);
    pack_wp_kernel<<<(Emb2 * Emb)  / 256, 256>>>(w_proj);

    qkv_hmma<<<dim3(E3 / 128, Mrows / 128), 256>>>(b_qkv);
    attn_hmma<<<dim3(Nseq / 64, Bsz * Hh), 128>>>();
    proj_hmma<<<dim3(Emb / 128, Mrows / 128), 256>>>(b_proj, out);
}

// round 14
// speedup vs baseline: 5.9791x; 1.0442x over previous
#include <cuda_runtime.h>
#include <cuda_fp16.h>
#include <math.h>

#define Bsz  2
#define Nseq 2048
#define Emb  1024
#define Hh   16
#define Dd   64
#define Mrows 4096
#define E3   3072
#define Emb2 512          // Emb/2  (packed pairs)
#define D2   32           // Dd/2

// Packed half2-in-uint scratch (scalar 32-bit global access only — safe envelope).
__device__ unsigned g_xh[Mrows * Emb2];          // x packed along E
__device__ unsigned g_wqh[Emb2 * E3];            // w_qkv packed along k (rows)
__device__ unsigned g_wph[Emb2 * Emb];           // w_proj packed along k
__device__ unsigned g_qh[Bsz * Hh * Nseq * D2];  // [B,H,N,D/2]
__device__ unsigned g_kh[Bsz * Hh * Nseq * D2];
__device__ unsigned g_vh[Bsz * Hh * Nseq * D2];
__device__ unsigned g_aoh[Mrows * Emb2];         // attention out packed [B*N, E/2]

__device__ __forceinline__ unsigned pack2(float lo, float hi) {
    unsigned ul = (unsigned)__half_as_ushort(__float2half_rn(lo));
    unsigned uh = (unsigned)__half_as_ushort(__float2half_rn(hi));
    return ul | (uh << 16);
}

// ---------------------------------------------------------------------------
// Prep kernels: pack fp32 inputs to half2 uints ONCE per launch.
// ---------------------------------------------------------------------------
__global__ __launch_bounds__(256) void pack_x_kernel(const float* __restrict__ x)
{
    const int i = blockIdx.x * 256 + threadIdx.x;
    g_xh[i] = pack2(x[2 * i], x[2 * i + 1]);
}

__global__ __launch_bounds__(256) void pack_wq_kernel(const float* __restrict__ w)
{
    const int i = blockIdx.x * 256 + threadIdx.x;
    const int k2 = i / E3;
    const int n  = i - k2 * E3;
    g_wqh[i] = pack2(w[k2 * (2 * E3) + n], w[k2 * (2 * E3) + E3 + n]);
}

__global__ __launch_bounds__(256) void pack_wp_kernel(const float* __restrict__ w)
{
    const int i = blockIdx.x * 256 + threadIdx.x;
    const int k2 = i >> 10;
    const int n  = i & (Emb - 1);
    g_wph[i] = pack2(w[k2 * (2 * Emb) + n], w[k2 * (2 * Emb) + Emb + n]);
}

// ---------------------------------------------------------------------------
// ldmatrix + fp16 m16n8k16 mma macros
// ---------------------------------------------------------------------------
#define LDSM4(dst, addr_)                                                     \
    asm volatile(                                                             \
        "ldmatrix.sync.aligned.m8n8.x4.shared.b16 {%0,%1,%2,%3}, [%4];"       \
        : "=r"((dst).x), "=r"((dst).y), "=r"((dst).z), "=r"((dst).w)          \
        : "r"(addr_));

#define MMA1(mt, nt)                                                          \
    asm volatile(                                                             \
        "mma.sync.aligned.m16n8k16.row.col.f32.f16.f16.f32 "                  \
        "{%0,%1,%2,%3}, {%4,%5,%6,%7}, {%8,%9}, {%0,%1,%2,%3};\n"             \
        : "+f"(c##mt##nt.x), "+f"(c##mt##nt.y),                               \
          "+f"(c##mt##nt.z), "+f"(c##mt##nt.w)                                \
        : "r"(a##mt.x), "r"(a##mt.y), "r"(a##mt.z), "r"(a##mt.w),             \
          "r"(b##nt.x), "r"(b##nt.y))

// A frag via one ldmatrix.x4 (rows wm+mt*16+(lane&15), pair-col kk2+(lane>>4)*4)
#define LDA(mt)                                                               \
    uint4 a##mt;                                                              \
    LDSM4(a##mt, aSm + 4u * (unsigned)(bufc * 2560 +                          \
          (wm + mt * 16 + lrow) * 20 + kk2 + lcol4));

// B frag (scalar LDS, packed k-pairs, conflict-free)
#define LDB(nt)                                                               \
    uint2 b##nt;                                                              \
    {                                                                         \
        const int col_ = wn + nt * 8 + g;                                     \
        b##nt.x = Bsu[bufc][kk2 + tig][col_];                                 \
        b##nt.y = Bsu[bufc][kk2 + tig + 4][col_];                             \
    }

#define DEF_C(mt)                                                             \
    float4 c##mt##0 = {0.f,0.f,0.f,0.f}, c##mt##1 = {0.f,0.f,0.f,0.f},        \
           c##mt##2 = {0.f,0.f,0.f,0.f}, c##mt##3 = {0.f,0.f,0.f,0.f};

__device__ __forceinline__ void qkv_store2(int row, int col, float v0, float v1) {
    const int part = col >> 10;           // 0=q,1=k,2=v
    const int h    = (col >> 6) & (Hh - 1);
    const int d2   = (col & (Dd - 1)) >> 1;
    const int bb   = row >> 11;
    const int tok  = row & (Nseq - 1);
    unsigned* dst = (part == 0) ? g_qh : ((part == 1) ? g_kh : g_vh);
    dst[(((bb * Hh + h) * Nseq) + tok) * D2 + d2] = pack2(v0, v1);
}

#define EPIQ(mt, nt)                                                          \
    {                                                                         \
        const int row_ = m0 + wm + mt * 16 + g;                               \
        const int col_ = n0 + wn + nt * 8 + 2 * tig;                          \
        qkv_store2(row_,     col_, c##mt##nt.x + bias[col_], c##mt##nt.y + bias[col_ + 1]); \
        qkv_store2(row_ + 8, col_, c##mt##nt.z + bias[col_], c##mt##nt.w + bias[col_ + 1]); \
    }

#define EPIP(mt, nt)                                                          \
    {                                                                         \
        const int row_ = m0 + wm + mt * 16 + g;                               \
        const int col_ = n0 + wn + nt * 8 + 2 * tig;                          \
        out[row_ * Emb + col_]           = c##mt##nt.x + bias[col_];          \
        out[row_ * Emb + col_ + 1]       = c##mt##nt.y + bias[col_ + 1];      \
        out[(row_ + 8) * Emb + col_]     = c##mt##nt.z + bias[col_];          \
        out[(row_ + 8) * Emb + col_ + 1] = c##mt##nt.w + bias[col_ + 1];      \
    }

#define GEMM_IDX                                                              \
    const int tid  = threadIdx.x;                                             \
    const int lane = tid & 31;                                                \
    const int w    = tid >> 5;                                                \
    const int g    = lane >> 2;                                               \
    const int tig  = lane & 3;                                                \
    const int wm   = (w >> 2) * 64;                                           \
    const int wn   = (w & 3) * 32;                                            \
    const int m0   = blockIdx.y * 128;                                        \
    const int n0   = blockIdx.x * 128;                                        \
    const int lrow = lane & 15;                                               \
    const int lcol4 = (lane >> 4) << 2;                                       \
    const int am   = tid >> 4;                                                \
    const int ak2  = tid & 15;                                                \
    const int bn   = tid & 127;                                               \
    const int bq   = tid >> 7;

#define LGA(j, koff2) pa##j = AELU(am + 16*(j), (koff2) + ak2);
#define LGB(j, koff2) pb##j = BELU((koff2) + bq + 2*(j), bn);
#define LG8(koff2) LGA(0,koff2) LGA(1,koff2) LGA(2,koff2) LGA(3,koff2)        \
                   LGA(4,koff2) LGA(5,koff2) LGA(6,koff2) LGA(7,koff2)        \
                   LGB(0,koff2) LGB(1,koff2) LGB(2,koff2) LGB(3,koff2)        \
                   LGB(4,koff2) LGB(5,koff2) LGB(6,koff2) LGB(7,koff2)
#define STA(j, bf) As2u[bf][am + 16*(j)][ak2] = pa##j;
#define STB(j, bf) Bsu[bf][bq + 2*(j)][bn] = pb##j;
#define ST8(bf) STA(0,bf) STA(1,bf) STA(2,bf) STA(3,bf)                       \
                STA(4,bf) STA(5,bf) STA(6,bf) STA(7,bf)                       \
                STB(0,bf) STB(1,bf) STB(2,bf) STB(3,bf)                       \
                STB(4,bf) STB(5,bf) STB(6,bf) STB(7,bf)

#define GEMM_MAIN_BODY                                                        \
    __shared__ unsigned As2u[2][128][20];                                     \
    __shared__ unsigned Bsu[2][16][136];                                      \
    GEMM_IDX                                                                  \
    const unsigned aSm = (unsigned)__cvta_generic_to_shared(&As2u[0][0][0]);  \
    DEF_C(0) DEF_C(1) DEF_C(2) DEF_C(3)                                       \
    unsigned pa0,pa1,pa2,pa3,pa4,pa5,pa6,pa7;                                 \
    unsigned pb0,pb1,pb2,pb3,pb4,pb5,pb6,pb7;                                 \
    LG8(0)                                                                    \
    ST8(0)                                                                    \
    __syncthreads();                                                          \
    for (int k2c = 0; k2c < Emb2; k2c += 16) {                                \
        const int bufc = (k2c >> 4) & 1;                                      \
        const bool more = (k2c + 16 < Emb2);                                  \
        if (more) { LG8(k2c + 16) }                                           \
        _Pragma("unroll")                                                     \
        for (int ks = 0; ks < 2; ks++) {                                      \
            const int kk2 = ks * 8;                                           \
            LDA(0) LDA(1) LDA(2) LDA(3)                                       \
            LDB(0) LDB(1) LDB(2) LDB(3)                                       \
            MMA1(0,0); MMA1(0,1); MMA1(0,2); MMA1(0,3);                       \
            MMA1(1,0); MMA1(1,1); MMA1(1,2); MMA1(1,3);                       \
            MMA1(2,0); MMA1(2,1); MMA1(2,2); MMA1(2,3);                       \
            MMA1(3,0); MMA1(3,1); MMA1(3,2); MMA1(3,3);                       \
        }                                                                     \
        if (more) { const int nb = bufc ^ 1; ST8(nb) }                        \
        __syncthreads();                                                      \
    }

// ---------------------------------------------------------------------------
// QKV GEMM: xh[4096,512] @ wqh[512,3072] + bias -> packed q/k/v
// ---------------------------------------------------------------------------
__global__ __launch_bounds__(256) void qkv_hmma(const float* __restrict__ bias)
{
#define AELU(mr, kc2) g_xh[(m0 + (mr)) * Emb2 + (kc2)]
#define BELU(kr2, nc) g_wqh[(kr2) * E3 + n0 + (nc)]
    GEMM_MAIN_BODY
#undef AELU
#undef BELU
    EPIQ(0,0) EPIQ(0,1) EPIQ(0,2) EPIQ(0,3)
    EPIQ(1,0) EPIQ(1,1) EPIQ(1,2) EPIQ(1,3)
    EPIQ(2,0) EPIQ(2,1) EPIQ(2,2) EPIQ(2,3)
    EPIQ(3,0) EPIQ(3,1) EPIQ(3,2) EPIQ(3,3)
}

// ---------------------------------------------------------------------------
// Output projection: aoh[4096,512] @ wph[512,1024] + bias -> d_out (fp32)
// ---------------------------------------------------------------------------
__global__ __launch_bounds__(256) void proj_hmma(
    const float* __restrict__ bias, float* __restrict__ out)
{
#define AELU(mr, kc2) g_aoh[(m0 + (mr)) * Emb2 + (kc2)]
#define BELU(kr2, nc) g_wph[(kr2) * Emb + n0 + (nc)]
    GEMM_MAIN_BODY
#undef AELU
#undef BELU
    EPIP(0,0) EPIP(0,1) EPIP(0,2) EPIP(0,3)
    EPIP(1,0) EPIP(1,1) EPIP(1,2) EPIP(1,3)
    EPIP(2,0) EPIP(2,1) EPIP(2,2) EPIP(2,3)
    EPIP(3,0) EPIP(3,1) EPIP(3,2) EPIP(3,3)
}

// ---------------------------------------------------------------------------
// Flash attention, fp16 mma. Block = 128 queries x (b,h); 8 warps x 16 queries.
// Q/K frags via ldmatrix; V via byte_perm; P register-resident; exp2 softmax.
// ---------------------------------------------------------------------------
#define SCL 0.18033688f    // 0.125 * log2(e)

#define MMA_FR(sacc, bx, by)                                                  \
    asm volatile(                                                             \
        "mma.sync.aligned.m16n8k16.row.col.f32.f16.f16.f32 "                  \
        "{%0,%1,%2,%3}, {%4,%5,%6,%7}, {%8,%9}, {%0,%1,%2,%3};\n"             \
        : "+f"(sacc.x), "+f"(sacc.y), "+f"(sacc.z), "+f"(sacc.w)              \
        : "r"(qa.x), "r"(qa.y), "r"(qa.z), "r"(qa.w), "r"(bx), "r"(by));

#define MMA_OV(nt)                                                            \
    {                                                                         \
        const int d2_ = nt * 4 + (g >> 1);                                    \
        const unsigned bx = __byte_perm(Vsu[kp0][d2_],   Vsu[kp0+1][d2_], psel); \
        const unsigned by = __byte_perm(Vsu[kp0+8][d2_], Vsu[kp0+9][d2_], psel); \
        asm volatile(                                                         \
            "mma.sync.aligned.m16n8k16.row.col.f32.f16.f16.f32 "              \
            "{%0,%1,%2,%3}, {%4,%5,%6,%7}, {%8,%9}, {%0,%1,%2,%3};\n"         \
            : "+f"(o##nt.x), "+f"(o##nt.y), "+f"(o##nt.z), "+f"(o##nt.w)      \
            : "r"(a0), "r"(a1), "r"(a2), "r"(a3), "r"(bx), "r"(by));          \
    }

#define PVSTEP(kt, sa, sb)                                                    \
    {                                                                         \
        const unsigned a0 = pack2(sa.x, sa.y);                                \
        const unsigned a1 = pack2(sa.z, sa.w);                                \
        const unsigned a2 = pack2(sb.x, sb.y);                                \
        const unsigned a3 = pack2(sb.z, sb.w);                                \
        const int kp0 = (kt) * 16 + 2 * tig;                                  \
        MMA_OV(0) MMA_OV(1) MMA_OV(2) MMA_OV(3)                               \
        MMA_OV(4) MMA_OV(5) MMA_OV(6) MMA_OV(7)                               \
    }

#define SMAX(nt)                                                              \
    { s##nt.x *= SCL; s##nt.y *= SCL; s##nt.z *= SCL; s##nt.w *= SCL;         \
      mx0 = fmaxf(mx0, fmaxf(s##nt.x, s##nt.y));                              \
      mx1 = fmaxf(mx1, fmaxf(s##nt.z, s##nt.w)); }

#define SEXP(nt)                                                              \
    { s##nt.x = exp2f(s##nt.x - nm0); s##nt.y = exp2f(s##nt.y - nm0);         \
      s##nt.z = exp2f(s##nt.z - nm1); s##nt.w = exp2f(s##nt.w - nm1);         \
      sum0 += s##nt.x + s##nt.y; sum1 += s##nt.z + s##nt.w; }

#define OCORR(nt)                                                             \
    { o##nt.x *= corr0; o##nt.y *= corr0; o##nt.z *= corr1; o##nt.w *= corr1; }

#define OSTORE(nt)                                                            \
    { dst0[nt * 4 + tig] = pack2(o##nt.x * inv0, o##nt.y * inv0);             \
      dst1[nt * 4 + tig] = pack2(o##nt.z * inv1, o##nt.w * inv1); }

__global__ __launch_bounds__(256) void attn_hmma()
{
    __shared__ unsigned Qsu[128][36];  // [q][d2]
    __shared__ unsigned Ksu[64][36];   // [key][d2]
    __shared__ unsigned Vsu[64][36];   // [key][d2]

    const int tid  = threadIdx.x;
    const int lane = tid & 31;
    const int w    = tid >> 5;          // warp 0..7 -> queries [16w,16w+16)
    const int g    = lane >> 2;
    const int tig  = lane & 3;
    const int bh   = blockIdx.y;
    const int q0   = blockIdx.x * 128;
    const int qr   = w * 16 + g;
    const unsigned psel = (g & 1) ? 0x7632u : 0x5410u;
    // ldmatrix lane addressing
    const int lrow  = lane & 15;             // A-frag rows
    const int lcol4 = (lane >> 4) << 2;      // A-frag pair-col offset
    const int krow  = ((lane >> 4) << 3) + (lane & 7);   // B-frag rows
    const int kcol4 = ((lane >> 3) & 1) << 2;            // B-frag pair-col

    const unsigned* Qg = g_qh + (size_t)(bh * Nseq + q0) * D2;
    const unsigned* Kg = g_kh + (size_t)bh * Nseq * D2;
    const unsigned* Vg = g_vh + (size_t)bh * Nseq * D2;

    #pragma unroll
    for (int u = 0; u < 16; u++) {
        const int e = tid + u * 256;
        Qsu[e >> 5][e & 31] = Qg[e];
    }

    const unsigned qSm = (unsigned)__cvta_generic_to_shared(&Qsu[0][0]);
    const unsigned kSm = (unsigned)__cvta_generic_to_shared(&Ksu[0][0]);

    float m0r = -INFINITY, m1r = -INFINITY, l0 = 0.0f, l1 = 0.0f;
    float4 o0 = {0.f,0.f,0.f,0.f}, o1 = {0.f,0.f,0.f,0.f},
           o2 = {0.f,0.f,0.f,0.f}, o3 = {0.f,0.f,0.f,0.f},
           o4 = {0.f,0.f,0.f,0.f}, o5 = {0.f,0.f,0.f,0.f},
           o6 = {0.f,0.f,0.f,0.f}, o7 = {0.f,0.f,0.f,0.f};
    __syncthreads();

    for (int t = 0; t < Nseq / 64; t++) {
        const unsigned* Kt = Kg + t * 64 * D2;
        const unsigned* Vt = Vg + t * 64 * D2;
        #pragma unroll
        for (int u = 0; u < 8; u++) {
            const int e = tid + u * 256;
            const int r = e >> 5, d2 = e & 31;
            Ksu[r][d2] = Kt[e];
            Vsu[r][d2] = Vt[e];
        }
        __syncthreads();

        // S = Q @ K^T  (16q x 64key per warp); frags via ldmatrix
        float4 s0 = {0.f,0.f,0.f,0.f}, s1 = {0.f,0.f,0.f,0.f},
               s2 = {0.f,0.f,0.f,0.f}, s3 = {0.f,0.f,0.f,0.f},
               s4 = {0.f,0.f,0.f,0.f}, s5 = {0.f,0.f,0.f,0.f},
               s6 = {0.f,0.f,0.f,0.f}, s7 = {0.f,0.f,0.f,0.f};
        #pragma unroll
        for (int ks = 0; ks < 4; ks++) {
            const int kk2 = ks * 8;
            uint4 qa;
            LDSM4(qa, qSm + 4u * (unsigned)((w * 16 + lrow) * 36 + kk2 + lcol4));
            {
                uint4 kb;
                LDSM4(kb, kSm + 4u * (unsigned)((krow) * 36 + kk2 + kcol4));
                MMA_FR(s0, kb.x, kb.y) MMA_FR(s1, kb.z, kb.w)
            }
            {
                uint4 kb;
                LDSM4(kb, kSm + 4u * (unsigned)((16 + krow) * 36 + kk2 + kcol4));
                MMA_FR(s2, kb.x, kb.y) MMA_FR(s3, kb.z, kb.w)
            }
            {
                uint4 kb;
                LDSM4(kb, kSm + 4u * (unsigned)((32 + krow) * 36 + kk2 + kcol4));
                MMA_FR(s4, kb.x, kb.y) MMA_FR(s5, kb.z, kb.w)
            }
            {
                uint4 kb;
                LDSM4(kb, kSm + 4u * (unsigned)((48 + krow) * 36 + kk2 + kcol4));
                MMA_FR(s6, kb.x, kb.y) MMA_FR(s7, kb.z, kb.w)
            }
        }

        // online softmax in log2 domain (rows qr, qr+8)
        float mx0 = -INFINITY, mx1 = -INFINITY;
        SMAX(0) SMAX(1) SMAX(2) SMAX(3) SMAX(4) SMAX(5) SMAX(6) SMAX(7)
        mx0 = fmaxf(mx0, __shfl_xor_sync(0xffffffffu, mx0, 1));
        mx0 = fmaxf(mx0, __shfl_xor_sync(0xffffffffu, mx0, 2));
        mx1 = fmaxf(mx1, __shfl_xor_sync(0xffffffffu, mx1, 1));
        mx1 = fmaxf(mx1, __shfl_xor_sync(0xffffffffu, mx1, 2));
        const float nm0 = fmaxf(m0r, mx0);
        const float nm1 = fmaxf(m1r, mx1);
        float sum0 = 0.0f, sum1 = 0.0f;
        SEXP(0) SEXP(1) SEXP(2) SEXP(3) SEXP(4) SEXP(5) SEXP(6) SEXP(7)
        sum0 += __shfl_xor_sync(0xffffffffu, sum0, 1);
        sum0 += __shfl_xor_sync(0xffffffffu, sum0, 2);
        sum1 += __shfl_xor_sync(0xffffffffu, sum1, 1);
        sum1 += __shfl_xor_sync(0xffffffffu, sum1, 2);
        const float corr0 = exp2f(m0r - nm0);   // exp2(-inf)=0 first iter
        const float corr1 = exp2f(m1r - nm1);
        l0 = l0 * corr0 + sum0;
        l1 = l1 * corr1 + sum1;
        m0r = nm0; m1r = nm1;
        OCORR(0) OCORR(1) OCORR(2) OCORR(3) OCORR(4) OCORR(5) OCORR(6) OCORR(7)

        // O += P @ V  — P passed register-to-register
        PVSTEP(0, s0, s1)
        PVSTEP(1, s2, s3)
        PVSTEP(2, s4, s5)
        PVSTEP(3, s6, s7)
        __syncthreads();
    }

    // epilogue: normalize + packed store to g_aoh [B*N, E/2]
    const int bb = bh >> 4;
    const int h  = bh & (Hh - 1);
    const float inv0 = 1.0f / l0;
    const float inv1 = 1.0f / l1;
    const int row0 = q0 + qr;
    unsigned* dst0 = &g_aoh[(size_t)(bb * Nseq + row0) * Emb2 + h * D2];
    unsigned* dst1 = &g_aoh[(size_t)(bb * Nseq + row0 + 8) * Emb2 + h * D2];
    OSTORE(0) OSTORE(1) OSTORE(2) OSTORE(3)
    OSTORE(4) OSTORE(5) OSTORE(6) OSTORE(7)
}

// ---------------------------------------------------------------------------
extern "C" void kernel_launch(void* const* d_in, const int* in_sizes, int n_in,
                              void* d_out, int out_size)
{
    const float* x      = (const float*)d_in[0];
    const float* w_qkv  = (const float*)d_in[1];
    const float* b_qkv  = (const float*)d_in[2];
    const float* w_proj = (const float*)d_in[3];
    const float* b_proj = (const float*)d_in[4];
    float* out = (float*)d_out;

    pack_x_kernel <<<(Mrows * Emb2) / 256, 256>>>(x);
    pack_wq_kernel<<<(Emb2 * E3)   / 256, 256>>>(w_qkv);
    pack_wp_kernel<<<(Emb2 * Emb)  / 256, 256>>>(w_proj);

    qkv_hmma<<<dim3(E3 / 128, Mrows / 128), 256>>>(b_qkv);
    attn_hmma<<<dim3(Nseq / 128, Bsz * Hh), 256>>>();
    proj_hmma<<<dim3(Emb / 128, Mrows / 128), 256>>>(b_proj, out);
}